// round 2
// baseline (speedup 1.0000x reference)
#include <cuda_runtime.h>
#include <cstdint>

#define NN 100000
#define EMAX 3200000
#define HH 4
#define CC 8
#define HC 32
#define GG 512
#define FIN 128
#define NEG 0.2f

// ---------------- scratch (static device globals; no allocation) ----------------
__device__ int      d_deg[NN];
__device__ int      d_rowoff[NN + 1];
__device__ int      d_cursor[NN];
__device__ int      d_csrsrc[EMAX];
__device__ float    d_h[NN * HC];        // per-layer transformed features
__device__ float    d_als[NN * HH];      // attention logits (src side)
__device__ float    d_ald[NN * HH];      // attention logits (dst side)
__device__ float    d_xbuf[NN * HC];     // layer activations (elu output)
__device__ unsigned d_asmax[HH];         // flipped-uint global max of al_s per head
__device__ float    d_gsum[GG * HC];
__device__ float    d_gcnt[GG];
__device__ int      d_is64_edge;
__device__ int      d_is64_batch;

// ---------------- helpers ----------------
__device__ __forceinline__ float lrelu(float x) { return fmaxf(x, NEG * x); }

__device__ __forceinline__ unsigned flipf(float f) {
    unsigned u = __float_as_uint(f);
    return (u & 0x80000000u) ? ~u : (u | 0x80000000u);
}
__device__ __forceinline__ float unflipf(unsigned u) {
    return (u & 0x80000000u) ? __uint_as_float(u ^ 0x80000000u) : __uint_as_float(~u);
}

// ---------------- dtype detection ----------------
// If indices are int64 (little-endian, values < 2^31), every odd 32-bit word is 0.
// Sample ranges stay within the int32-sized buffers so reads are in-bounds either way.
__global__ void detect_kernel(const unsigned* __restrict__ e, const unsigned* __restrict__ b) {
    int t = threadIdx.x;                       // 256 threads
    int anyE = 0, anyB = 0;
    for (int k = t; k < 1024; k += 256) anyE |= (e[2 * k + 1] != 0u);
    for (int k = 2000 + t; k < 6000; k += 256) anyB |= (b[2 * k + 1] != 0u);
    __shared__ int sE, sB;
    if (t == 0) { sE = 0; sB = 0; }
    __syncthreads();
    if (anyE) atomicOr(&sE, 1);
    if (anyB) atomicOr(&sB, 1);
    __syncthreads();
    if (t == 0) { d_is64_edge = !sE; d_is64_batch = !sB; }
}

// ---------------- CSR build ----------------
__global__ void zero_deg_kernel() {
    int i = blockIdx.x * blockDim.x + threadIdx.x;
    if (i < NN) d_deg[i] = 0;
}

__global__ void count_kernel(const void* __restrict__ eidx, int E) {
    int e = blockIdx.x * blockDim.x + threadIdx.x;
    if (e >= E) return;
    int dst;
    if (d_is64_edge) dst = (int)((const long long*)eidx)[(size_t)E + e];
    else             dst = ((const int*)eidx)[(size_t)E + e];
    atomicAdd(&d_deg[dst], 1);
}

__global__ void scan_kernel() {
    __shared__ int sums[1024];
    int t = threadIdx.x;
    const int CH = (NN + 1023) / 1024;   // 98
    int beg = t * CH;
    int end = min(beg + CH, NN);
    int s = 0;
    for (int i = beg; i < end; i++) s += d_deg[i];
    sums[t] = s;
    __syncthreads();
    for (int off = 1; off < 1024; off <<= 1) {
        int v = (t >= off) ? sums[t - off] : 0;
        __syncthreads();
        sums[t] += v;
        __syncthreads();
    }
    int run = (t == 0) ? 0 : sums[t - 1];
    for (int i = beg; i < end; i++) {
        d_rowoff[i] = run;
        d_cursor[i] = run;
        run += d_deg[i];
    }
    if (t == 1023) d_rowoff[NN] = sums[1023];
}

__global__ void scatter_kernel(const void* __restrict__ eidx, int E) {
    int e = blockIdx.x * blockDim.x + threadIdx.x;
    if (e >= E) return;
    int s, dst;
    if (d_is64_edge) {
        s   = (int)((const long long*)eidx)[e];
        dst = (int)((const long long*)eidx)[(size_t)E + e];
    } else {
        s   = ((const int*)eidx)[e];
        dst = ((const int*)eidx)[(size_t)E + e];
    }
    int pos = atomicAdd(&d_cursor[dst], 1);
    d_csrsrc[pos] = s;
}

// ---------------- per-layer node transform ----------------
__global__ void zero_asmax_kernel() {
    if (threadIdx.x < HH) d_asmax[threadIdx.x] = 0u;
}

// Layer 1: h = x @ W (128 -> 32), plus attention logits + global max(al_s)
__global__ void k1_first_kernel(const float* __restrict__ x, const float* __restrict__ W,
                                const float* __restrict__ as_, const float* __restrict__ ad_) {
    __shared__ float sW[FIN * HC];
    __shared__ unsigned smax[HH];
    int t = threadIdx.x;                       // 256
    for (int i = t; i < FIN * HC; i += 256) sW[i] = W[i];
    if (t < HH) smax[t] = 0u;
    __syncthreads();

    int lane = t & 31, w = t >> 5;
    int n = blockIdx.x * 8 + w;                // grid 12500 exact
    float av_s = as_[lane], av_d = ad_[lane];

    float4 xv = ((const float4*)(x + (size_t)n * FIN))[lane];
    float hc = 0.f;
#pragma unroll
    for (int k = 0; k < FIN; k++) {
        float comp = ((k & 3) == 0) ? xv.x : ((k & 3) == 1) ? xv.y : ((k & 3) == 2) ? xv.z : xv.w;
        float xk = __shfl_sync(0xffffffffu, comp, k >> 2);
        hc = fmaf(xk, sW[k * HC + lane], hc);
    }

    float ps = hc * av_s, pd = hc * av_d;
    ps += __shfl_xor_sync(0xffffffffu, ps, 1);
    ps += __shfl_xor_sync(0xffffffffu, ps, 2);
    ps += __shfl_xor_sync(0xffffffffu, ps, 4);
    pd += __shfl_xor_sync(0xffffffffu, pd, 1);
    pd += __shfl_xor_sync(0xffffffffu, pd, 2);
    pd += __shfl_xor_sync(0xffffffffu, pd, 4);

    d_h[(size_t)n * HC + lane] = hc;
    int head = lane >> 3;
    if ((lane & 7) == 0) {
        d_als[n * HH + head] = ps;
        d_ald[n * HH + head] = pd;
        atomicMax(&smax[head], flipf(ps));
    }
    __syncthreads();
    if (t < HH) atomicMax(&d_asmax[t], smax[t]);
}

// Layers 2-4: h = xbuf @ W (32 -> 32), same epilogue
__global__ void k1_small_kernel(const float* __restrict__ W,
                                const float* __restrict__ as_, const float* __restrict__ ad_) {
    __shared__ float sW[HC * HC];
    __shared__ unsigned smax[HH];
    int t = threadIdx.x;                       // 256
    for (int i = t; i < HC * HC; i += 256) sW[i] = W[i];
    if (t < HH) smax[t] = 0u;
    __syncthreads();

    int lane = t & 31, w = t >> 5;
    int n = blockIdx.x * 8 + w;
    float av_s = as_[lane], av_d = ad_[lane];

    float xi = d_xbuf[(size_t)n * HC + lane];
    float hc = 0.f;
#pragma unroll
    for (int k = 0; k < HC; k++) {
        float xk = __shfl_sync(0xffffffffu, xi, k);
        hc = fmaf(xk, sW[k * HC + lane], hc);
    }

    float ps = hc * av_s, pd = hc * av_d;
    ps += __shfl_xor_sync(0xffffffffu, ps, 1);
    ps += __shfl_xor_sync(0xffffffffu, ps, 2);
    ps += __shfl_xor_sync(0xffffffffu, ps, 4);
    pd += __shfl_xor_sync(0xffffffffu, pd, 1);
    pd += __shfl_xor_sync(0xffffffffu, pd, 2);
    pd += __shfl_xor_sync(0xffffffffu, pd, 4);

    d_h[(size_t)n * HC + lane] = hc;
    int head = lane >> 3;
    if ((lane & 7) == 0) {
        d_als[n * HH + head] = ps;
        d_ald[n * HH + head] = pd;
        atomicMax(&smax[head], flipf(ps));
    }
    __syncthreads();
    if (t < HH) atomicMax(&d_asmax[t], smax[t]);
}

// ---------------- edge aggregation: one warp per dst node ----------------
// Global-bound softmax shift: exp(e - m_bound) with
// m_bound = lrelu(max_n al_s[n,h] + al_d[d,h]) >= every e into d (lrelu monotone).
// Mathematically identical alpha; one edge pass instead of two.
__global__ void edge_kernel(const float* __restrict__ bias) {
    int t = threadIdx.x, lane = t & 31;
    int d = blockIdx.x * 8 + (t >> 5);         // grid 12500 exact
    int head = lane >> 3;

    float ald_h = __ldg(&d_ald[d * HH + head]);
    float mh = lrelu(unflipf(d_asmax[head]) + ald_h);

    // self loop
    float als_d = __ldg(&d_als[d * HH + head]);
    float ee = __expf(lrelu(als_d + ald_h) - mh);
    float denom = ee;
    float acc = ee * __ldg(&d_h[(size_t)d * HC + lane]);

    int beg = d_rowoff[d], end = d_rowoff[d + 1];
    for (int base = beg; base < end; base += 32) {
        int m = end - base; if (m > 32) m = 32;
        int s = 0;
        if (base + lane < end) s = __ldg(&d_csrsrc[base + lane]);
#pragma unroll 8
        for (int j = 0; j < m; j++) {
            int sj = __shfl_sync(0xffffffffu, s, j);
            float e = lrelu(__ldg(&d_als[sj * HH + head]) + ald_h);
            float w = __expf(e - mh);
            denom += w;
            acc = fmaf(w, __ldg(&d_h[(size_t)sj * HC + lane]), acc);
        }
    }
    float out = acc / denom + bias[lane];
    d_xbuf[(size_t)d * HC + lane] = (out > 0.f) ? out : (__expf(out) - 1.f);
}

// ---------------- pooling + fc ----------------
__global__ void zero_pool_kernel() {
    int i = blockIdx.x * blockDim.x + threadIdx.x;
    if (i < GG * HC) d_gsum[i] = 0.f;
    if (i < GG) d_gcnt[i] = 0.f;
}

__global__ void pool_kernel(const void* __restrict__ batch) {
    int t = threadIdx.x, lane = t & 31;
    int n = blockIdx.x * 8 + (t >> 5);
    if (n >= NN) return;
    int g;
    if (d_is64_batch) g = (int)((const long long*)batch)[n];
    else              g = ((const int*)batch)[n];
    atomicAdd(&d_gsum[g * HC + lane], d_xbuf[(size_t)n * HC + lane]);
    if (lane == 0) atomicAdd(&d_gcnt[g], 1.0f);
}

__global__ void final_kernel(const float* __restrict__ fc_w, const float* __restrict__ fc_b,
                             float* __restrict__ out) {
    int g = blockIdx.x * blockDim.x + threadIdx.x;
    if (g >= GG) return;
    float inv = 1.0f / fmaxf(d_gcnt[g], 1.0f);
    float s = 0.f;
#pragma unroll
    for (int c = 0; c < HC; c++) s = fmaf(d_gsum[g * HC + c] * inv, fc_w[c], s);
    out[g] = s + fc_b[0];
}

// ---------------- launch ----------------
extern "C" void kernel_launch(void* const* d_in, const int* in_sizes, int n_in,
                              void* d_out, int out_size) {
    const float* x     = (const float*)d_in[0];
    const void*  eidx  = d_in[1];
    const void*  batch = d_in[2];
    // per-layer params: W, a_src, a_dst, b at 3 + 4*(L-1)
    const float* W1  = (const float*)d_in[3];
    const float* as1 = (const float*)d_in[4];
    const float* ad1 = (const float*)d_in[5];
    const float* b1  = (const float*)d_in[6];
    const float* fc_w = (const float*)d_in[19];
    const float* fc_b = (const float*)d_in[20];
    float* out = (float*)d_out;

    int E = in_sizes[1] / 2;
    if (E > EMAX) E = EMAX;
    if (E < 0) E = 0;

    const int NB = NN / 8;                 // 12500 blocks of 8 warps
    const int EB = (E + 255) / 256;

    detect_kernel<<<1, 256>>>((const unsigned*)eidx, (const unsigned*)batch);

    // CSR build
    zero_deg_kernel<<<(NN + 255) / 256, 256>>>();
    if (EB > 0) count_kernel<<<EB, 256>>>(eidx, E);
    scan_kernel<<<1, 1024>>>();
    if (EB > 0) scatter_kernel<<<EB, 256>>>(eidx, E);

    // Layer 1 (input dim 128)
    zero_asmax_kernel<<<1, 32>>>();
    k1_first_kernel<<<NB, 256>>>(x, W1, as1, ad1);
    edge_kernel<<<NB, 256>>>(b1);

    // Layers 2-4 (input dim 32)
    for (int L = 1; L < 4; L++) {
        const float* W   = (const float*)d_in[3 + 4 * L];
        const float* as_ = (const float*)d_in[4 + 4 * L];
        const float* ad_ = (const float*)d_in[5 + 4 * L];
        const float* b_  = (const float*)d_in[6 + 4 * L];
        zero_asmax_kernel<<<1, 32>>>();
        k1_small_kernel<<<NB, 256>>>(W, as_, ad_);
        edge_kernel<<<NB, 256>>>(b_);
    }

    // Global mean pool + FC
    zero_pool_kernel<<<(GG * HC + 255) / 256, 256>>>();
    pool_kernel<<<NB, 256>>>(batch);
    final_kernel<<<2, 256>>>(fc_w, fc_b, out);
}

// round 3
// speedup vs baseline: 1.2583x; 1.2583x over previous
#include <cuda_runtime.h>
#include <cstdint>

#define NN 100000
#define EMAX 3200000
#define HH 4
#define CC 8
#define HC 32
#define GG 512
#define FIN 128
#define NEG 0.2f

#define SB 1024
#define NBLK ((NN + SB - 1) / SB)   // 98

// ---------------- scratch (static device globals; no allocation) ----------------
__device__ int      d_deg[NN];
__device__ int      d_rowoff[NN + 1];
__device__ int      d_cursor[NN];
__device__ int      d_csrsrc[EMAX];
__device__ int      d_bsum[NBLK];
__device__ int      d_bbase[NBLK];
__device__ float    d_h[NN * HC];        // per-layer transformed features
__device__ float    d_als[NN * HH];      // attention logits (src side), float4 rows
__device__ float    d_ald[NN * HH];      // attention logits (dst side), float4 rows
__device__ float    d_xbuf[NN * HC];     // layer activations (elu output)
__device__ unsigned d_asmax[HH];         // flipped-uint global max of al_s per head
__device__ float    d_gsum[GG * HC];
__device__ float    d_gcnt[GG];
__device__ int      d_is64_edge;
__device__ int      d_is64_batch;

// ---------------- helpers ----------------
__device__ __forceinline__ float lrelu(float x) { return fmaxf(x, NEG * x); }

__device__ __forceinline__ unsigned flipf(float f) {
    unsigned u = __float_as_uint(f);
    return (u & 0x80000000u) ? ~u : (u | 0x80000000u);
}
__device__ __forceinline__ float unflipf(unsigned u) {
    return (u & 0x80000000u) ? __uint_as_float(u ^ 0x80000000u) : __uint_as_float(~u);
}

// ---------------- dtype detection ----------------
__global__ void detect_kernel(const unsigned* __restrict__ e, const unsigned* __restrict__ b) {
    int t = threadIdx.x;                       // 256 threads
    int anyE = 0, anyB = 0;
    for (int k = t; k < 1024; k += 256) anyE |= (e[2 * k + 1] != 0u);
    for (int k = 2000 + t; k < 6000; k += 256) anyB |= (b[2 * k + 1] != 0u);
    __shared__ int sE, sB;
    if (t == 0) { sE = 0; sB = 0; }
    __syncthreads();
    if (anyE) atomicOr(&sE, 1);
    if (anyB) atomicOr(&sB, 1);
    __syncthreads();
    if (t == 0) { d_is64_edge = !sE; d_is64_batch = !sB; }
}

// ---------------- CSR build ----------------
__global__ void zero_deg_kernel() {
    int i = blockIdx.x * blockDim.x + threadIdx.x;
    if (i < NN) d_deg[i] = 0;
}

__global__ void count_kernel(const void* __restrict__ eidx, int E) {
    int e = blockIdx.x * blockDim.x + threadIdx.x;
    if (e >= E) return;
    int dst;
    if (d_is64_edge) dst = (int)((const long long*)eidx)[(size_t)E + e];
    else             dst = ((const int*)eidx)[(size_t)E + e];
    atomicAdd(&d_deg[dst], 1);
}

// phase 1: per-block sums of deg
__global__ void scan_part1() {
    __shared__ int red[32];
    int t = threadIdx.x;
    int i = blockIdx.x * SB + t;
    int v = (i < NN) ? d_deg[i] : 0;
    int s = v;
    s += __shfl_xor_sync(0xffffffffu, s, 1);
    s += __shfl_xor_sync(0xffffffffu, s, 2);
    s += __shfl_xor_sync(0xffffffffu, s, 4);
    s += __shfl_xor_sync(0xffffffffu, s, 8);
    s += __shfl_xor_sync(0xffffffffu, s, 16);
    if ((t & 31) == 0) red[t >> 5] = s;
    __syncthreads();
    if (t < 32) {
        int x = red[t];
        x += __shfl_xor_sync(0xffffffffu, x, 1);
        x += __shfl_xor_sync(0xffffffffu, x, 2);
        x += __shfl_xor_sync(0xffffffffu, x, 4);
        x += __shfl_xor_sync(0xffffffffu, x, 8);
        x += __shfl_xor_sync(0xffffffffu, x, 16);
        if (t == 0) d_bsum[blockIdx.x] = x;
    }
}

// phase 2: scan the 98 block sums (one small block)
__global__ void scan_part2() {
    __shared__ int sh[128];
    int t = threadIdx.x;                       // 128
    int v = (t < NBLK) ? d_bsum[t] : 0;
    sh[t] = v;
    __syncthreads();
    for (int off = 1; off < 128; off <<= 1) {
        int x = (t >= off) ? sh[t - off] : 0;
        __syncthreads();
        sh[t] += x;
        __syncthreads();
    }
    if (t < NBLK) d_bbase[t] = sh[t] - v;      // exclusive base
    if (t == NBLK - 1) d_rowoff[NN] = sh[t];
}

// phase 3: local exclusive scan + base
__global__ void scan_part3() {
    __shared__ int sh[SB];
    int t = threadIdx.x;
    int i = blockIdx.x * SB + t;
    int v = (i < NN) ? d_deg[i] : 0;
    sh[t] = v;
    __syncthreads();
    for (int off = 1; off < SB; off <<= 1) {
        int x = (t >= off) ? sh[t - off] : 0;
        __syncthreads();
        sh[t] += x;
        __syncthreads();
    }
    int off = d_bbase[blockIdx.x] + sh[t] - v;
    if (i < NN) { d_rowoff[i] = off; d_cursor[i] = off; }
}

__global__ void scatter_kernel(const void* __restrict__ eidx, int E) {
    int e = blockIdx.x * blockDim.x + threadIdx.x;
    if (e >= E) return;
    int s, dst;
    if (d_is64_edge) {
        s   = (int)((const long long*)eidx)[e];
        dst = (int)((const long long*)eidx)[(size_t)E + e];
    } else {
        s   = ((const int*)eidx)[e];
        dst = ((const int*)eidx)[(size_t)E + e];
    }
    int pos = atomicAdd(&d_cursor[dst], 1);
    d_csrsrc[pos] = s;
}

// ---------------- per-layer node transform ----------------
__global__ void zero_asmax_kernel() {
    if (threadIdx.x < HH) d_asmax[threadIdx.x] = 0u;
}

// Layer 1: h = x @ W (128 -> 32), plus attention logits + global max(al_s)
__global__ void k1_first_kernel(const float* __restrict__ x, const float* __restrict__ W,
                                const float* __restrict__ as_, const float* __restrict__ ad_) {
    __shared__ float sW[FIN * HC];
    __shared__ unsigned smax[HH];
    int t = threadIdx.x;                       // 256
    for (int i = t; i < FIN * HC; i += 256) sW[i] = W[i];
    if (t < HH) smax[t] = 0u;
    __syncthreads();

    int lane = t & 31, w = t >> 5;
    int n = blockIdx.x * 8 + w;                // grid 12500 exact
    float av_s = as_[lane], av_d = ad_[lane];

    float4 xv = ((const float4*)(x + (size_t)n * FIN))[lane];
    float hc = 0.f;
#pragma unroll
    for (int k = 0; k < FIN; k++) {
        float comp = ((k & 3) == 0) ? xv.x : ((k & 3) == 1) ? xv.y : ((k & 3) == 2) ? xv.z : xv.w;
        float xk = __shfl_sync(0xffffffffu, comp, k >> 2);
        hc = fmaf(xk, sW[k * HC + lane], hc);
    }

    float ps = hc * av_s, pd = hc * av_d;
    ps += __shfl_xor_sync(0xffffffffu, ps, 1);
    ps += __shfl_xor_sync(0xffffffffu, ps, 2);
    ps += __shfl_xor_sync(0xffffffffu, ps, 4);
    pd += __shfl_xor_sync(0xffffffffu, pd, 1);
    pd += __shfl_xor_sync(0xffffffffu, pd, 2);
    pd += __shfl_xor_sync(0xffffffffu, pd, 4);

    d_h[(size_t)n * HC + lane] = hc;
    int head = lane >> 3;
    if ((lane & 7) == 0) {
        d_als[n * HH + head] = ps;
        d_ald[n * HH + head] = pd;
        atomicMax(&smax[head], flipf(ps));
    }
    __syncthreads();
    if (t < HH) atomicMax(&d_asmax[t], smax[t]);
}

// Layers 2-4: h = xbuf @ W (32 -> 32), same epilogue
__global__ void k1_small_kernel(const float* __restrict__ W,
                                const float* __restrict__ as_, const float* __restrict__ ad_) {
    __shared__ float sW[HC * HC];
    __shared__ unsigned smax[HH];
    int t = threadIdx.x;                       // 256
    for (int i = t; i < HC * HC; i += 256) sW[i] = W[i];
    if (t < HH) smax[t] = 0u;
    __syncthreads();

    int lane = t & 31, w = t >> 5;
    int n = blockIdx.x * 8 + w;
    float av_s = as_[lane], av_d = ad_[lane];

    float xi = d_xbuf[(size_t)n * HC + lane];
    float hc = 0.f;
#pragma unroll
    for (int k = 0; k < HC; k++) {
        float xk = __shfl_sync(0xffffffffu, xi, k);
        hc = fmaf(xk, sW[k * HC + lane], hc);
    }

    float ps = hc * av_s, pd = hc * av_d;
    ps += __shfl_xor_sync(0xffffffffu, ps, 1);
    ps += __shfl_xor_sync(0xffffffffu, ps, 2);
    ps += __shfl_xor_sync(0xffffffffu, ps, 4);
    pd += __shfl_xor_sync(0xffffffffu, pd, 1);
    pd += __shfl_xor_sync(0xffffffffu, pd, 2);
    pd += __shfl_xor_sync(0xffffffffu, pd, 4);

    d_h[(size_t)n * HC + lane] = hc;
    int head = lane >> 3;
    if ((lane & 7) == 0) {
        d_als[n * HH + head] = ps;
        d_ald[n * HH + head] = pd;
        atomicMax(&smax[head], flipf(ps));
    }
    __syncthreads();
    if (t < HH) atomicMax(&d_asmax[t], smax[t]);
}

// ---------------- edge aggregation: one warp per dst node ----------------
// Softmax via global upper bound m_h = lrelu(max_n al_s[n,h] + al_d[d,h]) (exact).
// Per 32-edge chunk: lane j owns edge j -> 1 float4 LDG of al_s row, 4 vector
// expf per chunk (vs 32 warp-wide), weights staged in smem for the
// channel-parallel accumulation pass.
__global__ void edge_kernel(const float* __restrict__ bias) {
    __shared__ float sw[8][32 * HH + 4];       // per-warp edge weights [j][head]
    int t = threadIdx.x, lane = t & 31, w = t >> 5;
    int d = blockIdx.x * 8 + w;                // grid 12500 exact
    int head = lane >> 3;
    float* swp = sw[w];

    float4 aldv = __ldg((const float4*)&d_ald[d * HH]);
    float m0 = lrelu(unflipf(d_asmax[0]) + aldv.x);
    float m1 = lrelu(unflipf(d_asmax[1]) + aldv.y);
    float m2 = lrelu(unflipf(d_asmax[2]) + aldv.z);
    float m3 = lrelu(unflipf(d_asmax[3]) + aldv.w);

    // self loop weight (uniform across lanes)
    float4 alsd = __ldg((const float4*)&d_als[d * HH]);
    float s0 = __expf(lrelu(alsd.x + aldv.x) - m0);
    float s1 = __expf(lrelu(alsd.y + aldv.y) - m1);
    float s2 = __expf(lrelu(alsd.z + aldv.z) - m2);
    float s3 = __expf(lrelu(alsd.w + aldv.w) - m3);
    float wself = (head == 0) ? s0 : (head == 1) ? s1 : (head == 2) ? s2 : s3;

    float acc = wself * __ldg(&d_h[(size_t)d * HC + lane]);
    float dn0 = 0.f, dn1 = 0.f, dn2 = 0.f, dn3 = 0.f;  // per-lane partial denoms

    int beg = d_rowoff[d], end = d_rowoff[d + 1];
    for (int base = beg; base < end; base += 32) {
        int idx = base + lane;
        bool v = idx < end;
        int s = v ? __ldg(&d_csrsrc[idx]) : 0;
        float4 a = __ldg((const float4*)&d_als[s * HH]);
        float w0 = __expf(lrelu(a.x + aldv.x) - m0);
        float w1 = __expf(lrelu(a.y + aldv.y) - m1);
        float w2 = __expf(lrelu(a.z + aldv.z) - m2);
        float w3 = __expf(lrelu(a.w + aldv.w) - m3);
        if (!v) { w0 = w1 = w2 = w3 = 0.f; }
        dn0 += w0; dn1 += w1; dn2 += w2; dn3 += w3;
        ((float4*)&swp[lane * HH])[0] = make_float4(w0, w1, w2, w3);
        __syncwarp();

        int m = end - base; if (m > 32) m = 32;
#pragma unroll 8
        for (int j = 0; j < m; j++) {
            int sj = __shfl_sync(0xffffffffu, s, j);
            float wj = swp[j * HH + head];
            acc = fmaf(wj, __ldg(&d_h[(size_t)sj * HC + lane]), acc);
        }
        __syncwarp();
    }

    // reduce per-component denominators across lanes
#pragma unroll
    for (int off = 1; off < 32; off <<= 1) {
        dn0 += __shfl_xor_sync(0xffffffffu, dn0, off);
        dn1 += __shfl_xor_sync(0xffffffffu, dn1, off);
        dn2 += __shfl_xor_sync(0xffffffffu, dn2, off);
        dn3 += __shfl_xor_sync(0xffffffffu, dn3, off);
    }
    float dh = (head == 0) ? dn0 : (head == 1) ? dn1 : (head == 2) ? dn2 : dn3;
    float denom = wself + dh;

    float out = acc / denom + bias[lane];
    d_xbuf[(size_t)d * HC + lane] = (out > 0.f) ? out : (__expf(out) - 1.f);
}

// ---------------- pooling + fc ----------------
__global__ void zero_pool_kernel() {
    int i = blockIdx.x * blockDim.x + threadIdx.x;
    if (i < GG * HC) d_gsum[i] = 0.f;
    if (i < GG) d_gcnt[i] = 0.f;
}

__global__ void pool_kernel(const void* __restrict__ batch) {
    int t = threadIdx.x, lane = t & 31;
    int n = blockIdx.x * 8 + (t >> 5);
    if (n >= NN) return;
    int g;
    if (d_is64_batch) g = (int)((const long long*)batch)[n];
    else              g = ((const int*)batch)[n];
    atomicAdd(&d_gsum[g * HC + lane], d_xbuf[(size_t)n * HC + lane]);
    if (lane == 0) atomicAdd(&d_gcnt[g], 1.0f);
}

__global__ void final_kernel(const float* __restrict__ fc_w, const float* __restrict__ fc_b,
                             float* __restrict__ out) {
    int g = blockIdx.x * blockDim.x + threadIdx.x;
    if (g >= GG) return;
    float inv = 1.0f / fmaxf(d_gcnt[g], 1.0f);
    float s = 0.f;
#pragma unroll
    for (int c = 0; c < HC; c++) s = fmaf(d_gsum[g * HC + c] * inv, fc_w[c], s);
    out[g] = s + fc_b[0];
}

// ---------------- launch ----------------
extern "C" void kernel_launch(void* const* d_in, const int* in_sizes, int n_in,
                              void* d_out, int out_size) {
    const float* x     = (const float*)d_in[0];
    const void*  eidx  = d_in[1];
    const void*  batch = d_in[2];
    const float* W1  = (const float*)d_in[3];
    const float* as1 = (const float*)d_in[4];
    const float* ad1 = (const float*)d_in[5];
    const float* b1  = (const float*)d_in[6];
    const float* fc_w = (const float*)d_in[19];
    const float* fc_b = (const float*)d_in[20];
    float* out = (float*)d_out;

    int E = in_sizes[1] / 2;
    if (E > EMAX) E = EMAX;
    if (E < 0) E = 0;

    const int NB = NN / 8;                 // 12500 blocks of 8 warps
    const int EB = (E + 255) / 256;

    detect_kernel<<<1, 256>>>((const unsigned*)eidx, (const unsigned*)batch);

    // CSR build (parallel 3-phase scan)
    zero_deg_kernel<<<(NN + 255) / 256, 256>>>();
    if (EB > 0) count_kernel<<<EB, 256>>>(eidx, E);
    scan_part1<<<NBLK, SB>>>();
    scan_part2<<<1, 128>>>();
    scan_part3<<<NBLK, SB>>>();
    if (EB > 0) scatter_kernel<<<EB, 256>>>(eidx, E);

    // Layer 1 (input dim 128)
    zero_asmax_kernel<<<1, 32>>>();
    k1_first_kernel<<<NB, 256>>>(x, W1, as1, ad1);
    edge_kernel<<<NB, 256>>>(b1);

    // Layers 2-4 (input dim 32)
    for (int L = 1; L < 4; L++) {
        const float* W   = (const float*)d_in[3 + 4 * L];
        const float* as_ = (const float*)d_in[4 + 4 * L];
        const float* ad_ = (const float*)d_in[5 + 4 * L];
        const float* b_  = (const float*)d_in[6 + 4 * L];
        zero_asmax_kernel<<<1, 32>>>();
        k1_small_kernel<<<NB, 256>>>(W, as_, ad_);
        edge_kernel<<<NB, 256>>>(b_);
    }

    // Global mean pool + FC
    zero_pool_kernel<<<(GG * HC + 255) / 256, 256>>>();
    pool_kernel<<<NB, 256>>>(batch);
    final_kernel<<<2, 256>>>(fc_w, fc_b, out);
}

// round 5
// speedup vs baseline: 1.3264x; 1.0541x over previous
#include <cuda_runtime.h>
#include <cstdint>

#define NN 100000
#define EMAX 3200000
#define HH 4
#define CC 8
#define HC 32
#define GG 512
#define FIN 128
#define NEG 0.2f

#define SB 1024
#define NBLK ((NN + SB - 1) / SB)   // 98

// ---------------- scratch (static device globals; no allocation) ----------------
__device__ int      d_deg[NN];
__device__ int      d_rowoff[NN + 1];
__device__ int      d_cursor[NN];
__device__ int      d_csrsrc[EMAX];
__device__ int      d_bsum[NBLK];
__device__ int      d_bbase[NBLK];
__device__ float    d_h[NN * HC];        // per-layer transformed features (float4 rows x8)
__device__ float    d_als[NN * HH];      // attention logits (src side), float4 rows
__device__ float    d_ald[NN * HH];      // attention logits (dst side), float4 rows
__device__ float    d_xbuf[NN * HC];     // layer activations (elu output)
__device__ unsigned d_asmax[HH];         // flipped-uint global max of al_s per head
__device__ float    d_gsum[GG * HC];
__device__ float    d_gcnt[GG];
__device__ int      d_is64_edge;
__device__ int      d_is64_batch;

// ---------------- helpers ----------------
__device__ __forceinline__ float lrelu(float x) { return fmaxf(x, NEG * x); }

__device__ __forceinline__ unsigned flipf(float f) {
    unsigned u = __float_as_uint(f);
    return (u & 0x80000000u) ? ~u : (u | 0x80000000u);
}
__device__ __forceinline__ float unflipf(unsigned u) {
    return (u & 0x80000000u) ? __uint_as_float(u ^ 0x80000000u) : __uint_as_float(~u);
}

// ---------------- dtype detection ----------------
__global__ void detect_kernel(const unsigned* __restrict__ e, const unsigned* __restrict__ b) {
    int t = threadIdx.x;                       // 256 threads
    int anyE = 0, anyB = 0;
    for (int k = t; k < 1024; k += 256) anyE |= (e[2 * k + 1] != 0u);
    for (int k = 2000 + t; k < 6000; k += 256) anyB |= (b[2 * k + 1] != 0u);
    __shared__ int sE, sB;
    if (t == 0) { sE = 0; sB = 0; }
    __syncthreads();
    if (anyE) atomicOr(&sE, 1);
    if (anyB) atomicOr(&sB, 1);
    __syncthreads();
    if (t == 0) { d_is64_edge = !sE; d_is64_batch = !sB; }
}

// ---------------- CSR build ----------------
__global__ void zero_deg_kernel() {
    int i = blockIdx.x * blockDim.x + threadIdx.x;
    if (i < NN) d_deg[i] = 0;
}

__global__ void count_kernel(const void* __restrict__ eidx, int E) {
    int e = blockIdx.x * blockDim.x + threadIdx.x;
    if (e >= E) return;
    int dst;
    if (d_is64_edge) dst = (int)((const long long*)eidx)[(size_t)E + e];
    else             dst = ((const int*)eidx)[(size_t)E + e];
    atomicAdd(&d_deg[dst], 1);
}

// phase 1: per-block sums of deg
__global__ void scan_part1() {
    __shared__ int red[32];
    int t = threadIdx.x;
    int i = blockIdx.x * SB + t;
    int v = (i < NN) ? d_deg[i] : 0;
    int s = v;
    s += __shfl_xor_sync(0xffffffffu, s, 1);
    s += __shfl_xor_sync(0xffffffffu, s, 2);
    s += __shfl_xor_sync(0xffffffffu, s, 4);
    s += __shfl_xor_sync(0xffffffffu, s, 8);
    s += __shfl_xor_sync(0xffffffffu, s, 16);
    if ((t & 31) == 0) red[t >> 5] = s;
    __syncthreads();
    if (t < 32) {
        int x = red[t];
        x += __shfl_xor_sync(0xffffffffu, x, 1);
        x += __shfl_xor_sync(0xffffffffu, x, 2);
        x += __shfl_xor_sync(0xffffffffu, x, 4);
        x += __shfl_xor_sync(0xffffffffu, x, 8);
        x += __shfl_xor_sync(0xffffffffu, x, 16);
        if (t == 0) d_bsum[blockIdx.x] = x;
    }
}

// phase 2: scan the 98 block sums (one small block)
__global__ void scan_part2() {
    __shared__ int sh[128];
    int t = threadIdx.x;                       // 128
    int v = (t < NBLK) ? d_bsum[t] : 0;
    sh[t] = v;
    __syncthreads();
    for (int off = 1; off < 128; off <<= 1) {
        int x = (t >= off) ? sh[t - off] : 0;
        __syncthreads();
        sh[t] += x;
        __syncthreads();
    }
    if (t < NBLK) d_bbase[t] = sh[t] - v;      // exclusive base
    if (t == NBLK - 1) d_rowoff[NN] = sh[t];
}

// phase 3: local exclusive scan + base
__global__ void scan_part3() {
    __shared__ int sh[SB];
    int t = threadIdx.x;
    int i = blockIdx.x * SB + t;
    int v = (i < NN) ? d_deg[i] : 0;
    sh[t] = v;
    __syncthreads();
    for (int off = 1; off < SB; off <<= 1) {
        int x = (t >= off) ? sh[t - off] : 0;
        __syncthreads();
        sh[t] += x;
        __syncthreads();
    }
    int off = d_bbase[blockIdx.x] + sh[t] - v;
    if (i < NN) { d_rowoff[i] = off; d_cursor[i] = off; }
}

__global__ void scatter_kernel(const void* __restrict__ eidx, int E) {
    int e = blockIdx.x * blockDim.x + threadIdx.x;
    if (e >= E) return;
    int s, dst;
    if (d_is64_edge) {
        s   = (int)((const long long*)eidx)[e];
        dst = (int)((const long long*)eidx)[(size_t)E + e];
    } else {
        s   = ((const int*)eidx)[e];
        dst = ((const int*)eidx)[(size_t)E + e];
    }
    int pos = atomicAdd(&d_cursor[dst], 1);
    d_csrsrc[pos] = s;
}

// ---------------- per-layer node transform ----------------
__global__ void zero_asmax_kernel() {
    if (threadIdx.x < HH) d_asmax[threadIdx.x] = 0u;
}

// Layer 1: h = x @ W (128 -> 32), plus attention logits + global max(al_s)
__global__ void k1_first_kernel(const float* __restrict__ x, const float* __restrict__ W,
                                const float* __restrict__ as_, const float* __restrict__ ad_) {
    __shared__ float sW[FIN * HC];
    __shared__ unsigned smax[HH];
    int t = threadIdx.x;                       // 256
    for (int i = t; i < FIN * HC; i += 256) sW[i] = W[i];
    if (t < HH) smax[t] = 0u;
    __syncthreads();

    int lane = t & 31, w = t >> 5;
    int n = blockIdx.x * 8 + w;                // grid 12500 exact
    float av_s = as_[lane], av_d = ad_[lane];

    float4 xv = ((const float4*)(x + (size_t)n * FIN))[lane];
    float hc = 0.f;
#pragma unroll
    for (int k = 0; k < FIN; k++) {
        float comp = ((k & 3) == 0) ? xv.x : ((k & 3) == 1) ? xv.y : ((k & 3) == 2) ? xv.z : xv.w;
        float xk = __shfl_sync(0xffffffffu, comp, k >> 2);
        hc = fmaf(xk, sW[k * HC + lane], hc);
    }

    float ps = hc * av_s, pd = hc * av_d;
    ps += __shfl_xor_sync(0xffffffffu, ps, 1);
    ps += __shfl_xor_sync(0xffffffffu, ps, 2);
    ps += __shfl_xor_sync(0xffffffffu, ps, 4);
    pd += __shfl_xor_sync(0xffffffffu, pd, 1);
    pd += __shfl_xor_sync(0xffffffffu, pd, 2);
    pd += __shfl_xor_sync(0xffffffffu, pd, 4);

    d_h[(size_t)n * HC + lane] = hc;
    int head = lane >> 3;
    if ((lane & 7) == 0) {
        d_als[n * HH + head] = ps;
        d_ald[n * HH + head] = pd;
        atomicMax(&smax[head], flipf(ps));
    }
    __syncthreads();
    if (t < HH) atomicMax(&d_asmax[t], smax[t]);
}

// Layers 2-4: h = xbuf @ W (32 -> 32), same epilogue
__global__ void k1_small_kernel(const float* __restrict__ W,
                                const float* __restrict__ as_, const float* __restrict__ ad_) {
    __shared__ float sW[HC * HC];
    __shared__ unsigned smax[HH];
    int t = threadIdx.x;                       // 256
    for (int i = t; i < HC * HC; i += 256) sW[i] = W[i];
    if (t < HH) smax[t] = 0u;
    __syncthreads();

    int lane = t & 31, w = t >> 5;
    int n = blockIdx.x * 8 + w;
    float av_s = as_[lane], av_d = ad_[lane];

    float xi = d_xbuf[(size_t)n * HC + lane];
    float hc = 0.f;
#pragma unroll
    for (int k = 0; k < HC; k++) {
        float xk = __shfl_sync(0xffffffffu, xi, k);
        hc = fmaf(xk, sW[k * HC + lane], hc);
    }

    float ps = hc * av_s, pd = hc * av_d;
    ps += __shfl_xor_sync(0xffffffffu, ps, 1);
    ps += __shfl_xor_sync(0xffffffffu, ps, 2);
    ps += __shfl_xor_sync(0xffffffffu, ps, 4);
    pd += __shfl_xor_sync(0xffffffffu, pd, 1);
    pd += __shfl_xor_sync(0xffffffffu, pd, 2);
    pd += __shfl_xor_sync(0xffffffffu, pd, 4);

    d_h[(size_t)n * HC + lane] = hc;
    int head = lane >> 3;
    if ((lane & 7) == 0) {
        d_als[n * HH + head] = ps;
        d_ald[n * HH + head] = pd;
        atomicMax(&smax[head], flipf(ps));
    }
    __syncthreads();
    if (t < HH) atomicMax(&d_asmax[t], smax[t]);
}

// ---------------- edge aggregation: one warp per dst node, 4 edges/iter ----------------
// Softmax via global upper bound m_h = lrelu(max_n al_s[n,h] + al_d[d,h]) (exact).
// Lane remap: q = lane&7 (channel quad), g = lane>>3 (edge slot). One warp-wide
// LDG.128 gathers the h-rows of 4 edges at once. Invalid-lane weights are zero,
// so the 8x4 accumulation sub-loop needs no bounds check and fully unrolls.
__global__ void edge_kernel(const float* __restrict__ bias) {
    __shared__ float4 sw[8][32];               // per-warp edge weights [j] = (w0..w3)
    int t = threadIdx.x, lane = t & 31, w = t >> 5;
    int d = blockIdx.x * 8 + w;                // grid 12500 exact
    int q = lane & 7, g = lane >> 3;
    int head = q >> 1;                         // head of this channel quad
    float4* swp = sw[w];
    const float4* h4 = (const float4*)d_h;

    float4 aldv = __ldg((const float4*)&d_ald[d * HH]);
    float m0 = lrelu(unflipf(d_asmax[0]) + aldv.x);
    float m1 = lrelu(unflipf(d_asmax[1]) + aldv.y);
    float m2 = lrelu(unflipf(d_asmax[2]) + aldv.z);
    float m3 = lrelu(unflipf(d_asmax[3]) + aldv.w);

    // self-loop weight per head
    float4 alsd = __ldg((const float4*)&d_als[d * HH]);
    float s0 = __expf(lrelu(alsd.x + aldv.x) - m0);
    float s1 = __expf(lrelu(alsd.y + aldv.y) - m1);
    float s2 = __expf(lrelu(alsd.z + aldv.z) - m2);
    float s3 = __expf(lrelu(alsd.w + aldv.w) - m3);
    float wselfq = (head == 0) ? s0 : (head == 1) ? s1 : (head == 2) ? s2 : s3;

    float4 acc = make_float4(0.f, 0.f, 0.f, 0.f);
    if (g == 0) {
        float4 hs = __ldg(&h4[(size_t)d * 8 + q]);
        acc.x = wselfq * hs.x; acc.y = wselfq * hs.y;
        acc.z = wselfq * hs.z; acc.w = wselfq * hs.w;
    }
    float dn0 = 0.f, dn1 = 0.f, dn2 = 0.f, dn3 = 0.f;

    int beg = d_rowoff[d], end = d_rowoff[d + 1];
    for (int base = beg; base < end; base += 32) {
        // phase A: lane j owns edge j — compute all 4 head weights
        int idx = base + lane;
        bool v = idx < end;
        int s = v ? __ldg(&d_csrsrc[idx]) : 0;
        float4 a = __ldg((const float4*)&d_als[s * HH]);
        float w0 = __expf(lrelu(a.x + aldv.x) - m0);
        float w1 = __expf(lrelu(a.y + aldv.y) - m1);
        float w2 = __expf(lrelu(a.z + aldv.z) - m2);
        float w3 = __expf(lrelu(a.w + aldv.w) - m3);
        if (!v) { w0 = w1 = w2 = w3 = 0.f; }
        dn0 += w0; dn1 += w1; dn2 += w2; dn3 += w3;
        swp[lane] = make_float4(w0, w1, w2, w3);
        __syncwarp();

        // phase B: 4 edges per iteration; lane handles quad q of edge sub*4+g
#pragma unroll
        for (int sub = 0; sub < 8; sub++) {
            int j = sub * 4 + g;
            int sj = __shfl_sync(0xffffffffu, s, j);
            float4 hv = __ldg(&h4[(size_t)sj * 8 + q]);
            float wj = ((const float*)swp)[j * 4 + head];
            acc.x = fmaf(wj, hv.x, acc.x);
            acc.y = fmaf(wj, hv.y, acc.y);
            acc.z = fmaf(wj, hv.z, acc.z);
            acc.w = fmaf(wj, hv.w, acc.w);
        }
        __syncwarp();
    }

    // reduce accumulators across the 4 edge-slot groups (same q)
    acc.x += __shfl_xor_sync(0xffffffffu, acc.x, 8);
    acc.y += __shfl_xor_sync(0xffffffffu, acc.y, 8);
    acc.z += __shfl_xor_sync(0xffffffffu, acc.z, 8);
    acc.w += __shfl_xor_sync(0xffffffffu, acc.w, 8);
    acc.x += __shfl_xor_sync(0xffffffffu, acc.x, 16);
    acc.y += __shfl_xor_sync(0xffffffffu, acc.y, 16);
    acc.z += __shfl_xor_sync(0xffffffffu, acc.z, 16);
    acc.w += __shfl_xor_sync(0xffffffffu, acc.w, 16);

    // reduce per-head denominators across all lanes
#pragma unroll
    for (int off = 1; off < 32; off <<= 1) {
        dn0 += __shfl_xor_sync(0xffffffffu, dn0, off);
        dn1 += __shfl_xor_sync(0xffffffffu, dn1, off);
        dn2 += __shfl_xor_sync(0xffffffffu, dn2, off);
        dn3 += __shfl_xor_sync(0xffffffffu, dn3, off);
    }

    if (lane < 8) {
        float dh = (head == 0) ? dn0 : (head == 1) ? dn1 : (head == 2) ? dn2 : dn3;
        float inv = 1.0f / (wselfq + dh);
        float4 bq = __ldg(&((const float4*)bias)[q]);
        float4 o;
        o.x = acc.x * inv + bq.x;
        o.y = acc.y * inv + bq.y;
        o.z = acc.z * inv + bq.z;
        o.w = acc.w * inv + bq.w;
        o.x = (o.x > 0.f) ? o.x : (__expf(o.x) - 1.f);
        o.y = (o.y > 0.f) ? o.y : (__expf(o.y) - 1.f);
        o.z = (o.z > 0.f) ? o.z : (__expf(o.z) - 1.f);
        o.w = (o.w > 0.f) ? o.w : (__expf(o.w) - 1.f);
        ((float4*)d_xbuf)[(size_t)d * 8 + q] = o;
    }
}

// ---------------- pooling + fc ----------------
__global__ void zero_pool_kernel() {
    int i = blockIdx.x * blockDim.x + threadIdx.x;
    if (i < GG * HC) d_gsum[i] = 0.f;
    if (i < GG) d_gcnt[i] = 0.f;
}

__global__ void pool_kernel(const void* __restrict__ batch) {
    int t = threadIdx.x, lane = t & 31;
    int n = blockIdx.x * 8 + (t >> 5);
    if (n >= NN) return;
    int g;
    if (d_is64_batch) g = (int)((const long long*)batch)[n];
    else              g = ((const int*)batch)[n];
    atomicAdd(&d_gsum[g * HC + lane], d_xbuf[(size_t)n * HC + lane]);
    if (lane == 0) atomicAdd(&d_gcnt[g], 1.0f);
}

__global__ void final_kernel(const float* __restrict__ fc_w, const float* __restrict__ fc_b,
                             float* __restrict__ out) {
    int g = blockIdx.x * blockDim.x + threadIdx.x;
    if (g >= GG) return;
    float inv = 1.0f / fmaxf(d_gcnt[g], 1.0f);
    float s = 0.f;
#pragma unroll
    for (int c = 0; c < HC; c++) s = fmaf(d_gsum[g * HC + c] * inv, fc_w[c], s);
    out[g] = s + fc_b[0];
}

// ---------------- launch ----------------
extern "C" void kernel_launch(void* const* d_in, const int* in_sizes, int n_in,
                              void* d_out, int out_size) {
    const float* x     = (const float*)d_in[0];
    const void*  eidx  = d_in[1];
    const void*  batch = d_in[2];
    const float* W1  = (const float*)d_in[3];
    const float* as1 = (const float*)d_in[4];
    const float* ad1 = (const float*)d_in[5];
    const float* b1  = (const float*)d_in[6];
    const float* fc_w = (const float*)d_in[19];
    const float* fc_b = (const float*)d_in[20];
    float* out = (float*)d_out;

    int E = in_sizes[1] / 2;
    if (E > EMAX) E = EMAX;
    if (E < 0) E = 0;

    const int NB = NN / 8;                 // 12500 blocks of 8 warps
    const int EB = (E + 255) / 256;

    detect_kernel<<<1, 256>>>((const unsigned*)eidx, (const unsigned*)batch);

    // CSR build (parallel 3-phase scan)
    zero_deg_kernel<<<(NN + 255) / 256, 256>>>();
    if (EB > 0) count_kernel<<<EB, 256>>>(eidx, E);
    scan_part1<<<NBLK, SB>>>();
    scan_part2<<<1, 128>>>();
    scan_part3<<<NBLK, SB>>>();
    if (EB > 0) scatter_kernel<<<EB, 256>>>(eidx, E);

    // Layer 1 (input dim 128)
    zero_asmax_kernel<<<1, 32>>>();
    k1_first_kernel<<<NB, 256>>>(x, W1, as1, ad1);
    edge_kernel<<<NB, 256>>>(b1);

    // Layers 2-4 (input dim 32)
    for (int L = 1; L < 4; L++) {
        const float* W   = (const float*)d_in[3 + 4 * L];
        const float* as_ = (const float*)d_in[4 + 4 * L];
        const float* ad_ = (const float*)d_in[5 + 4 * L];
        const float* b_  = (const float*)d_in[6 + 4 * L];
        zero_asmax_kernel<<<1, 32>>>();
        k1_small_kernel<<<NB, 256>>>(W, as_, ad_);
        edge_kernel<<<NB, 256>>>(b_);
    }

    // Global mean pool + FC
    zero_pool_kernel<<<(GG * HC + 255) / 256, 256>>>();
    pool_kernel<<<NB, 256>>>(batch);
    final_kernel<<<2, 256>>>(fc_w, fc_b, out);
}

// round 6
// speedup vs baseline: 1.4218x; 1.0720x over previous
#include <cuda_runtime.h>
#include <cuda_fp16.h>
#include <cstdint>

#define NN 100000
#define EMAX 3200000
#define HH 4
#define CC 8
#define HC 32
#define GG 512
#define FIN 128
#define NEG 0.2f

#define SB 1024
#define NBLK ((NN + SB - 1) / SB)   // 98

// ---------------- scratch (static device globals; no allocation) ----------------
__device__ int      d_deg[NN];
__device__ int      d_rowoff[NN + 1];
__device__ int      d_cursor[NN];
__device__ int      d_csrsrc[EMAX];
__device__ int      d_bsum[NBLK];
__device__ int      d_bbase[NBLK];
__device__ __half   d_h16[NN * HC];      // fp16 transformed features, 64B rows
__device__ float    d_als[NN * HH];      // attention logits (src side), float4 rows
__device__ float    d_ald[NN * HH];      // attention logits (dst side), float4 rows
__device__ float    d_xbuf[NN * HC];     // layer activations (elu output), fp32
__device__ unsigned d_asmax[HH];         // flipped-uint global max of al_s per head
__device__ float    d_gsum[GG * HC];
__device__ float    d_gcnt[GG];
__device__ int      d_is64_edge;
__device__ int      d_is64_batch;

// ---------------- helpers ----------------
__device__ __forceinline__ float lrelu(float x) { return fmaxf(x, NEG * x); }

__device__ __forceinline__ unsigned flipf(float f) {
    unsigned u = __float_as_uint(f);
    return (u & 0x80000000u) ? ~u : (u | 0x80000000u);
}
__device__ __forceinline__ float unflipf(unsigned u) {
    return (u & 0x80000000u) ? __uint_as_float(u ^ 0x80000000u) : __uint_as_float(~u);
}

// ---------------- dtype detection ----------------
__global__ void detect_kernel(const unsigned* __restrict__ e, const unsigned* __restrict__ b) {
    int t = threadIdx.x;                       // 256 threads
    int anyE = 0, anyB = 0;
    for (int k = t; k < 1024; k += 256) anyE |= (e[2 * k + 1] != 0u);
    for (int k = 2000 + t; k < 6000; k += 256) anyB |= (b[2 * k + 1] != 0u);
    __shared__ int sE, sB;
    if (t == 0) { sE = 0; sB = 0; }
    __syncthreads();
    if (anyE) atomicOr(&sE, 1);
    if (anyB) atomicOr(&sB, 1);
    __syncthreads();
    if (t == 0) { d_is64_edge = !sE; d_is64_batch = !sB; }
}

// ---------------- CSR build ----------------
__global__ void zero_deg_kernel() {
    int i = blockIdx.x * blockDim.x + threadIdx.x;
    if (i < NN) d_deg[i] = 0;
}

__global__ void count_kernel(const void* __restrict__ eidx, int E) {
    int e = blockIdx.x * blockDim.x + threadIdx.x;
    if (e >= E) return;
    int dst;
    if (d_is64_edge) dst = (int)((const long long*)eidx)[(size_t)E + e];
    else             dst = ((const int*)eidx)[(size_t)E + e];
    atomicAdd(&d_deg[dst], 1);
}

// phase 1: per-block sums of deg
__global__ void scan_part1() {
    __shared__ int red[32];
    int t = threadIdx.x;
    int i = blockIdx.x * SB + t;
    int v = (i < NN) ? d_deg[i] : 0;
    int s = v;
    s += __shfl_xor_sync(0xffffffffu, s, 1);
    s += __shfl_xor_sync(0xffffffffu, s, 2);
    s += __shfl_xor_sync(0xffffffffu, s, 4);
    s += __shfl_xor_sync(0xffffffffu, s, 8);
    s += __shfl_xor_sync(0xffffffffu, s, 16);
    if ((t & 31) == 0) red[t >> 5] = s;
    __syncthreads();
    if (t < 32) {
        int x = red[t];
        x += __shfl_xor_sync(0xffffffffu, x, 1);
        x += __shfl_xor_sync(0xffffffffu, x, 2);
        x += __shfl_xor_sync(0xffffffffu, x, 4);
        x += __shfl_xor_sync(0xffffffffu, x, 8);
        x += __shfl_xor_sync(0xffffffffu, x, 16);
        if (t == 0) d_bsum[blockIdx.x] = x;
    }
}

// phase 2: scan the 98 block sums
__global__ void scan_part2() {
    __shared__ int sh[128];
    int t = threadIdx.x;                       // 128
    int v = (t < NBLK) ? d_bsum[t] : 0;
    sh[t] = v;
    __syncthreads();
    for (int off = 1; off < 128; off <<= 1) {
        int x = (t >= off) ? sh[t - off] : 0;
        __syncthreads();
        sh[t] += x;
        __syncthreads();
    }
    if (t < NBLK) d_bbase[t] = sh[t] - v;      // exclusive base
    if (t == NBLK - 1) d_rowoff[NN] = sh[t];
}

// phase 3: local exclusive scan + base
__global__ void scan_part3() {
    __shared__ int sh[SB];
    int t = threadIdx.x;
    int i = blockIdx.x * SB + t;
    int v = (i < NN) ? d_deg[i] : 0;
    sh[t] = v;
    __syncthreads();
    for (int off = 1; off < SB; off <<= 1) {
        int x = (t >= off) ? sh[t - off] : 0;
        __syncthreads();
        sh[t] += x;
        __syncthreads();
    }
    int off = d_bbase[blockIdx.x] + sh[t] - v;
    if (i < NN) { d_rowoff[i] = off; d_cursor[i] = off; }
}

__global__ void scatter_kernel(const void* __restrict__ eidx, int E) {
    int e = blockIdx.x * blockDim.x + threadIdx.x;
    if (e >= E) return;
    int s, dst;
    if (d_is64_edge) {
        s   = (int)((const long long*)eidx)[e];
        dst = (int)((const long long*)eidx)[(size_t)E + e];
    } else {
        s   = ((const int*)eidx)[e];
        dst = ((const int*)eidx)[(size_t)E + e];
    }
    int pos = atomicAdd(&d_cursor[dst], 1);
    d_csrsrc[pos] = s;
}

// ---------------- per-layer node transform ----------------
__global__ void zero_asmax_kernel() {
    if (threadIdx.x < HH) d_asmax[threadIdx.x] = 0u;
}

// Layer 1: h = x @ W (128 -> 32), plus attention logits + global max(al_s)
__global__ void k1_first_kernel(const float* __restrict__ x, const float* __restrict__ W,
                                const float* __restrict__ as_, const float* __restrict__ ad_) {
    __shared__ float sW[FIN * HC];
    __shared__ unsigned smax[HH];
    int t = threadIdx.x;                       // 256
    for (int i = t; i < FIN * HC; i += 256) sW[i] = W[i];
    if (t < HH) smax[t] = 0u;
    __syncthreads();

    int lane = t & 31, w = t >> 5;
    int n = blockIdx.x * 8 + w;                // grid 12500 exact
    float av_s = as_[lane], av_d = ad_[lane];

    float4 xv = ((const float4*)(x + (size_t)n * FIN))[lane];
    float hc = 0.f;
#pragma unroll
    for (int k = 0; k < FIN; k++) {
        float comp = ((k & 3) == 0) ? xv.x : ((k & 3) == 1) ? xv.y : ((k & 3) == 2) ? xv.z : xv.w;
        float xk = __shfl_sync(0xffffffffu, comp, k >> 2);
        hc = fmaf(xk, sW[k * HC + lane], hc);
    }

    float ps = hc * av_s, pd = hc * av_d;
    ps += __shfl_xor_sync(0xffffffffu, ps, 1);
    ps += __shfl_xor_sync(0xffffffffu, ps, 2);
    ps += __shfl_xor_sync(0xffffffffu, ps, 4);
    pd += __shfl_xor_sync(0xffffffffu, pd, 1);
    pd += __shfl_xor_sync(0xffffffffu, pd, 2);
    pd += __shfl_xor_sync(0xffffffffu, pd, 4);

    d_h16[(size_t)n * HC + lane] = __float2half(hc);
    int head = lane >> 3;
    if ((lane & 7) == 0) {
        d_als[n * HH + head] = ps;
        d_ald[n * HH + head] = pd;
        atomicMax(&smax[head], flipf(ps));
    }
    __syncthreads();
    if (t < HH) atomicMax(&d_asmax[t], smax[t]);
}

// Layers 2-4: h = xbuf @ W (32 -> 32), same epilogue
__global__ void k1_small_kernel(const float* __restrict__ W,
                                const float* __restrict__ as_, const float* __restrict__ ad_) {
    __shared__ float sW[HC * HC];
    __shared__ unsigned smax[HH];
    int t = threadIdx.x;                       // 256
    for (int i = t; i < HC * HC; i += 256) sW[i] = W[i];
    if (t < HH) smax[t] = 0u;
    __syncthreads();

    int lane = t & 31, w = t >> 5;
    int n = blockIdx.x * 8 + w;
    float av_s = as_[lane], av_d = ad_[lane];

    float xi = d_xbuf[(size_t)n * HC + lane];
    float hc = 0.f;
#pragma unroll
    for (int k = 0; k < HC; k++) {
        float xk = __shfl_sync(0xffffffffu, xi, k);
        hc = fmaf(xk, sW[k * HC + lane], hc);
    }

    float ps = hc * av_s, pd = hc * av_d;
    ps += __shfl_xor_sync(0xffffffffu, ps, 1);
    ps += __shfl_xor_sync(0xffffffffu, ps, 2);
    ps += __shfl_xor_sync(0xffffffffu, ps, 4);
    pd += __shfl_xor_sync(0xffffffffu, pd, 1);
    pd += __shfl_xor_sync(0xffffffffu, pd, 2);
    pd += __shfl_xor_sync(0xffffffffu, pd, 4);

    d_h16[(size_t)n * HC + lane] = __float2half(hc);
    int head = lane >> 3;
    if ((lane & 7) == 0) {
        d_als[n * HH + head] = ps;
        d_ald[n * HH + head] = pd;
        atomicMax(&smax[head], flipf(ps));
    }
    __syncthreads();
    if (t < HH) atomicMax(&d_asmax[t], smax[t]);
}

// ---------------- edge aggregation: one warp per dst node, fp16 rows ----------------
// Softmax via global upper bound m_h = lrelu(max_n al_s[n,h] + al_d[d,h]) (exact).
// q = lane&7 owns channels 4q..4q+3 (head q>>1); g = lane>>3 = edge slot.
// One warp-wide LDG.64 gathers the fp16 h-rows of 4 edges (64B/row).
__global__ void edge_kernel(const float* __restrict__ bias) {
    __shared__ float4 sw[8][32];               // per-warp edge weights [j] = (w0..w3)
    int t = threadIdx.x, lane = t & 31, w = t >> 5;
    int d = blockIdx.x * 8 + w;                // grid 12500 exact
    int q = lane & 7, g = lane >> 3;
    int head = q >> 1;                         // head of this 4-channel group
    float4* swp = sw[w];
    const uint2* h2 = (const uint2*)d_h16;     // 8B = 4 fp16 channels

    float4 aldv = __ldg((const float4*)&d_ald[d * HH]);
    float m0 = lrelu(unflipf(d_asmax[0]) + aldv.x);
    float m1 = lrelu(unflipf(d_asmax[1]) + aldv.y);
    float m2 = lrelu(unflipf(d_asmax[2]) + aldv.z);
    float m3 = lrelu(unflipf(d_asmax[3]) + aldv.w);

    // self-loop weight per head
    float4 alsd = __ldg((const float4*)&d_als[d * HH]);
    float s0 = __expf(lrelu(alsd.x + aldv.x) - m0);
    float s1 = __expf(lrelu(alsd.y + aldv.y) - m1);
    float s2 = __expf(lrelu(alsd.z + aldv.z) - m2);
    float s3 = __expf(lrelu(alsd.w + aldv.w) - m3);
    float wselfq = (head == 0) ? s0 : (head == 1) ? s1 : (head == 2) ? s2 : s3;

    float4 acc = make_float4(0.f, 0.f, 0.f, 0.f);
    if (g == 0) {
        uint2 hv = __ldg(&h2[(size_t)d * 8 + q]);
        float2 f0 = __half22float2(*(const __half2*)&hv.x);
        float2 f1 = __half22float2(*(const __half2*)&hv.y);
        acc.x = wselfq * f0.x; acc.y = wselfq * f0.y;
        acc.z = wselfq * f1.x; acc.w = wselfq * f1.y;
    }
    float dn0 = 0.f, dn1 = 0.f, dn2 = 0.f, dn3 = 0.f;

    int beg = d_rowoff[d], end = d_rowoff[d + 1];
    for (int base = beg; base < end; base += 32) {
        // phase A: lane j owns edge j — compute all 4 head weights
        int idx = base + lane;
        bool v = idx < end;
        int s = v ? __ldg(&d_csrsrc[idx]) : 0;
        float4 a = __ldg((const float4*)&d_als[s * HH]);
        float w0 = __expf(lrelu(a.x + aldv.x) - m0);
        float w1 = __expf(lrelu(a.y + aldv.y) - m1);
        float w2 = __expf(lrelu(a.z + aldv.z) - m2);
        float w3 = __expf(lrelu(a.w + aldv.w) - m3);
        if (!v) { w0 = w1 = w2 = w3 = 0.f; }
        dn0 += w0; dn1 += w1; dn2 += w2; dn3 += w3;
        swp[lane] = make_float4(w0, w1, w2, w3);
        __syncwarp();

        // phase B: 4 edges per iteration; lane handles 4-channel group q of edge sub*4+g
#pragma unroll
        for (int sub = 0; sub < 8; sub++) {
            int j = sub * 4 + g;
            int sj = __shfl_sync(0xffffffffu, s, j);
            uint2 hv = __ldg(&h2[(size_t)sj * 8 + q]);
            float wj = ((const float*)swp)[j * 4 + head];
            float2 f0 = __half22float2(*(const __half2*)&hv.x);
            float2 f1 = __half22float2(*(const __half2*)&hv.y);
            acc.x = fmaf(wj, f0.x, acc.x);
            acc.y = fmaf(wj, f0.y, acc.y);
            acc.z = fmaf(wj, f1.x, acc.z);
            acc.w = fmaf(wj, f1.y, acc.w);
        }
        __syncwarp();
    }

    // reduce accumulators across the 4 edge-slot groups (same q)
    acc.x += __shfl_xor_sync(0xffffffffu, acc.x, 8);
    acc.y += __shfl_xor_sync(0xffffffffu, acc.y, 8);
    acc.z += __shfl_xor_sync(0xffffffffu, acc.z, 8);
    acc.w += __shfl_xor_sync(0xffffffffu, acc.w, 8);
    acc.x += __shfl_xor_sync(0xffffffffu, acc.x, 16);
    acc.y += __shfl_xor_sync(0xffffffffu, acc.y, 16);
    acc.z += __shfl_xor_sync(0xffffffffu, acc.z, 16);
    acc.w += __shfl_xor_sync(0xffffffffu, acc.w, 16);

    // reduce per-head denominators across all lanes
#pragma unroll
    for (int off = 1; off < 32; off <<= 1) {
        dn0 += __shfl_xor_sync(0xffffffffu, dn0, off);
        dn1 += __shfl_xor_sync(0xffffffffu, dn1, off);
        dn2 += __shfl_xor_sync(0xffffffffu, dn2, off);
        dn3 += __shfl_xor_sync(0xffffffffu, dn3, off);
    }

    if (lane < 8) {
        float dh = (head == 0) ? dn0 : (head == 1) ? dn1 : (head == 2) ? dn2 : dn3;
        float inv = 1.0f / (wselfq + dh);
        float4 bq = __ldg(&((const float4*)bias)[q]);
        float4 o;
        o.x = acc.x * inv + bq.x;
        o.y = acc.y * inv + bq.y;
        o.z = acc.z * inv + bq.z;
        o.w = acc.w * inv + bq.w;
        o.x = (o.x > 0.f) ? o.x : (__expf(o.x) - 1.f);
        o.y = (o.y > 0.f) ? o.y : (__expf(o.y) - 1.f);
        o.z = (o.z > 0.f) ? o.z : (__expf(o.z) - 1.f);
        o.w = (o.w > 0.f) ? o.w : (__expf(o.w) - 1.f);
        ((float4*)d_xbuf)[(size_t)d * 8 + q] = o;
    }
}

// ---------------- pooling + fc ----------------
__global__ void zero_pool_kernel() {
    int i = blockIdx.x * blockDim.x + threadIdx.x;
    if (i < GG * HC) d_gsum[i] = 0.f;
    if (i < GG) d_gcnt[i] = 0.f;
}

__global__ void pool_kernel(const void* __restrict__ batch) {
    int t = threadIdx.x, lane = t & 31;
    int n = blockIdx.x * 8 + (t >> 5);
    if (n >= NN) return;
    int g;
    if (d_is64_batch) g = (int)((const long long*)batch)[n];
    else              g = ((const int*)batch)[n];
    atomicAdd(&d_gsum[g * HC + lane], d_xbuf[(size_t)n * HC + lane]);
    if (lane == 0) atomicAdd(&d_gcnt[g], 1.0f);
}

__global__ void final_kernel(const float* __restrict__ fc_w, const float* __restrict__ fc_b,
                             float* __restrict__ out) {
    int g = blockIdx.x * blockDim.x + threadIdx.x;
    if (g >= GG) return;
    float inv = 1.0f / fmaxf(d_gcnt[g], 1.0f);
    float s = 0.f;
#pragma unroll
    for (int c = 0; c < HC; c++) s = fmaf(d_gsum[g * HC + c] * inv, fc_w[c], s);
    out[g] = s + fc_b[0];
}

// ---------------- launch ----------------
extern "C" void kernel_launch(void* const* d_in, const int* in_sizes, int n_in,
                              void* d_out, int out_size) {
    const float* x     = (const float*)d_in[0];
    const void*  eidx  = d_in[1];
    const void*  batch = d_in[2];
    const float* W1  = (const float*)d_in[3];
    const float* as1 = (const float*)d_in[4];
    const float* ad1 = (const float*)d_in[5];
    const float* b1  = (const float*)d_in[6];
    const float* fc_w = (const float*)d_in[19];
    const float* fc_b = (const float*)d_in[20];
    float* out = (float*)d_out;

    int E = in_sizes[1] / 2;
    if (E > EMAX) E = EMAX;
    if (E < 0) E = 0;

    const int NB = NN / 8;                 // 12500 blocks of 8 warps
    const int EB = (E + 255) / 256;

    detect_kernel<<<1, 256>>>((const unsigned*)eidx, (const unsigned*)batch);

    // CSR build (parallel 3-phase scan)
    zero_deg_kernel<<<(NN + 255) / 256, 256>>>();
    if (EB > 0) count_kernel<<<EB, 256>>>(eidx, E);
    scan_part1<<<NBLK, SB>>>();
    scan_part2<<<1, 128>>>();
    scan_part3<<<NBLK, SB>>>();
    if (EB > 0) scatter_kernel<<<EB, 256>>>(eidx, E);

    // Layer 1 (input dim 128)
    zero_asmax_kernel<<<1, 32>>>();
    k1_first_kernel<<<NB, 256>>>(x, W1, as1, ad1);
    edge_kernel<<<NB, 256>>>(b1);

    // Layers 2-4 (input dim 32)
    for (int L = 1; L < 4; L++) {
        const float* W   = (const float*)d_in[3 + 4 * L];
        const float* as_ = (const float*)d_in[4 + 4 * L];
        const float* ad_ = (const float*)d_in[5 + 4 * L];
        const float* b_  = (const float*)d_in[6 + 4 * L];
        zero_asmax_kernel<<<1, 32>>>();
        k1_small_kernel<<<NB, 256>>>(W, as_, ad_);
        edge_kernel<<<NB, 256>>>(b_);
    }

    // Global mean pool + FC
    zero_pool_kernel<<<(GG * HC + 255) / 256, 256>>>();
    pool_kernel<<<NB, 256>>>(batch);
    final_kernel<<<2, 256>>>(fc_w, fc_b, out);
}